// round 9
// baseline (speedup 1.0000x reference)
#include <cuda_runtime.h>

#define Hh 256
#define Ww 704
#define HW (Hh*Ww)      // 180224 = 176*256*4
#define W4 (Ww/4)       // 176
#define CIMG 256
#define COUTC 131

// Scratch (device globals; no allocation allowed)
__device__ float4 d_gpart4[8 * (HW/4)];   // 8 channel-slab partial sums of gated
__device__ float d_spt[HW];
__device__ float d_v2[9*COUTC];
__device__ float d_u0[9*35];
__device__ float d_u1[9*67];
__device__ float d_wg[9];
__device__ float d_Ksum[9];               // [rowclass*3+colclass] bias sums

// ---------------------------------------------------------------------------
// Setup: block 0 folds weights; blocks 1..88 zero d_spt (512 threads each).
// ---------------------------------------------------------------------------
__global__ void setup_kernel(const float* __restrict__ sp_w,
                             const float* __restrict__ rd0_w,
                             const float* __restrict__ rd1_w,
                             const float* __restrict__ rd0_b,
                             const float* __restrict__ rd1_b,
                             const float* __restrict__ rd2_w,
                             const float* __restrict__ rd2_b,
                             const float* __restrict__ rd3_b) {
    int tid = threadIdx.x;
    if (blockIdx.x > 0) {
        ((float4*)d_spt)[(blockIdx.x - 1) * 512 + tid] = make_float4(0.f,0.f,0.f,0.f);
        return;
    }
    __shared__ float sK[9];
    for (int idx = tid; idx < 9*COUTC; idx += blockDim.x) {
        int t = idx / COUTC, j = idx % COUTC;
        float a = 0.f;
        for (int c = 0; c < COUTC; ++c) a += sp_w[c*9 + t] * rd2_w[c*COUTC + j];
        d_v2[idx] = a;
    }
    __syncthreads();
    for (int idx = tid; idx < 9*35; idx += blockDim.x) {
        int t = idx / 35, i = idx % 35;
        float a = 0.f;
        for (int j = 0; j < COUTC; ++j) a += d_v2[t*COUTC + j] * rd0_w[j*35 + i];
        d_u0[idx] = a;
    }
    for (int idx = tid; idx < 9*67; idx += blockDim.x) {
        int t = idx / 67, i = idx % 67;
        float a = 0.f;
        for (int j = 0; j < COUTC; ++j) a += d_v2[t*COUTC + j] * rd1_w[j*67 + i];
        d_u1[idx] = a;
    }
    if (tid < 9) {
        int t = tid;
        float w = 0.f, k = 0.f;
        for (int c = 0; c < COUTC; ++c) {
            w += sp_w[c*9 + t];
            k += d_v2[t*COUTC + c] * (rd0_b[c] + rd1_b[c]) + sp_w[c*9 + t] * rd2_b[c];
        }
        d_wg[t] = w;
        sK[t]   = k + w * rd3_b[0];
    }
    __syncthreads();
    if (tid < 9) {
        int rc = tid / 3, cc = tid % 3;
        float s = 0.f;
        for (int ty = 0; ty < 3; ++ty) {
            if ((rc == 0 && ty == 0) || (rc == 2 && ty == 2)) continue;
            for (int tx = 0; tx < 3; ++tx) {
                if ((cc == 0 && tx == 0) || (cc == 2 && tx == 2)) continue;
                s += sK[ty*3 + tx];
            }
        }
        d_Ksum[tid] = s;
    }
}

// ---------------------------------------------------------------------------
// Gated slabs: block = (slab cb, pixel-chunk pb of 512 float4); each thread
// owns TWO float4 pixels -> 64 outstanding loads, 704 gated blocks total.
// ---------------------------------------------------------------------------
__device__ __forceinline__ void gated_part(const float* __restrict__ img,
                                           const float* __restrict__ rd3_w,
                                           int b) {
    __shared__ float sw[32];
    int pb = b % 88, cb = b / 88;
    int c0 = cb * 32;
    if (threadIdx.x < 32) sw[threadIdx.x] = rd3_w[c0 + threadIdx.x];
    __syncthreads();
    int p4 = pb * 512 + threadIdx.x;
    const float4* base = (const float4*)img + (size_t)c0 * (HW/4) + p4;
    float4 a0 = make_float4(0.f, 0.f, 0.f, 0.f);
    float4 a1 = make_float4(0.f, 0.f, 0.f, 0.f);
    #pragma unroll
    for (int c = 0; c < 32; ++c) {
        float w = sw[c];
        float4 x0 = __ldcs(base + (size_t)c * (HW/4));
        float4 x1 = __ldcs(base + (size_t)c * (HW/4) + 256);
        a0.x += w * x0.x; a0.y += w * x0.y; a0.z += w * x0.z; a0.w += w * x0.w;
        a1.x += w * x1.x; a1.y += w * x1.y; a1.z += w * x1.z; a1.w += w * x1.w;
    }
    d_gpart4[cb * (HW/4) + p4]       = a0;
    d_gpart4[cb * (HW/4) + p4 + 256] = a1;
}

// ---------------------------------------------------------------------------
// Scatter, thread-per-point: feature row loaded once per point (float4),
// tap weights via smem float4 broadcasts, 9 spread atomicAdds per point.
// ---------------------------------------------------------------------------
template<int CF>
__device__ __forceinline__ void scatter_level(const float* __restrict__ feat,
                                              const float* __restrict__ coord,
                                              const int* __restrict__ grid,
                                              int N, const float* __restrict__ u,
                                              int blockInLevel) {
    constexpr int L  = CF + 3;
    constexpr int NC = CF/4 + 1;               // float4 chunks incl. coord tail
    __shared__ __align__(16) float4 suT[NC * 9];
    for (int idx = threadIdx.x; idx < NC * 9 * 4; idx += blockDim.x) {
        int c = idx & 3, jt = idx >> 2;
        int t = jt % 9, j = jt / 9;
        int i = 4 * j + c;
        ((float*)&suT[j * 9 + t])[c] = (i < L) ? u[t * L + i] : 0.f;
    }
    __syncthreads();
    int n = blockInLevel * 256 + threadIdx.x;
    if (n >= N) return;
    float acc[9];
    #pragma unroll
    for (int t = 0; t < 9; ++t) acc[t] = 0.f;
    const float4* fp = (const float4*)(feat + (size_t)n * CF);
    #pragma unroll
    for (int j = 0; j < CF/4; ++j) {
        float4 p = __ldg(fp + j);
        #pragma unroll
        for (int t = 0; t < 9; ++t) {
            float4 w = suT[j * 9 + t];
            acc[t] += w.x*p.x + w.y*p.y + w.z*p.z + w.w*p.w;
        }
    }
    float c0 = __ldg(coord + n*3 + 0);
    float c1 = __ldg(coord + n*3 + 1);
    float c2 = __ldg(coord + n*3 + 2);
    #pragma unroll
    for (int t = 0; t < 9; ++t) {
        float4 w = suT[(CF/4) * 9 + t];
        acc[t] += w.x*c0 + w.y*c1 + w.z*c2;
    }
    int2 gxy = __ldg((const int2*)grid + n);   // (col, row)
    #pragma unroll
    for (int t = 0; t < 9; ++t) {
        int h = gxy.y - t/3 + 1;
        int w = gxy.x - t%3 + 1;
        if (h >= 0 && h < Hh && w >= 0 && w < Ww)
            atomicAdd(&d_spt[h * Ww + w], acc[t]);
    }
}

#define GB 704   // gated blocks (88 x 8)

// Combined gated + scatter, Bresenham-interleaved roles (proven in r8).
__global__ void work_kernel(const float* __restrict__ img, const float* __restrict__ rd3_w,
                            const float* __restrict__ f0, const float* __restrict__ c0,
                            const int* __restrict__ g0, int N0,
                            const float* __restrict__ f1, const float* __restrict__ c1,
                            const int* __restrict__ g1, int N1,
                            const float* __restrict__ f2, const float* __restrict__ c2,
                            const int* __restrict__ g2, int N2,
                            int sb0, int sb1, int sb2) {
    int SB = sb0 + sb1 + sb2;
    int total = SB + GB;
    int b = blockIdx.x;
    long long prod = (long long)b * SB;
    int sc_before = (int)(prod / total);
    int sc_incl   = (int)((prod + SB) / total);
    if (sc_incl > sc_before) {
        int s = sc_before;
        if (s < sb0) {
            scatter_level<32>(f0, c0, g0, N0, d_u0, s);
        } else if (s < sb0 + sb1) {
            scatter_level<64>(f1, c1, g1, N1, d_u1, s - sb0);
        } else {
            scatter_level<128>(f2, c2, g2, N2, d_v2, s - sb0 - sb1);
        }
    } else {
        gated_part(img, rd3_w, b - sc_before);
    }
}

// ---------------------------------------------------------------------------
// Fused att+mul: grid (256 rows, 4 channel-groups of 64). Each block computes
// its row's 704 att values in smem (gpart stencil + spt + sigmoid; ~67KB of
// L2-resident reads, 4x redundant across channel-groups), then streams
// 64 channels x 704 pixels of img -> out for that row.
// ---------------------------------------------------------------------------
__global__ void attmul_kernel(const float* __restrict__ img,
                              float* __restrict__ out,
                              const float* __restrict__ sp_b) {
    __shared__ __align__(16) float sm[3][712];   // stencil cols at [4 .. 708)
    __shared__ __align__(16) float satt[704];
    __shared__ float swg[9], sks[9];
    int h = blockIdx.x, cg = blockIdx.y, tid = threadIdx.x;
    if (tid < 9)  swg[tid] = d_wg[tid];
    else if (tid < 18) sks[tid - 9] = d_Ksum[tid - 9];
    if (tid < 176) {
        #pragma unroll
        for (int r = 0; r < 3; ++r) {
            int y = h + r - 1;
            float4 s = make_float4(0.f, 0.f, 0.f, 0.f);
            if (y >= 0 && y < Hh) {
                #pragma unroll
                for (int sl = 0; sl < 8; ++sl) {
                    float4 v = __ldg(&d_gpart4[sl * (HW/4) + y * W4 + tid]);
                    s.x += v.x; s.y += v.y; s.z += v.z; s.w += v.w;
                }
            }
            *(float4*)&sm[r][4 + 4*tid] = s;
            if (tid == 0) { sm[r][3] = 0.f; sm[r][708] = 0.f; }
        }
    }
    __syncthreads();
    if (tid < 176) {
        float bias = sp_b[0];
        int rc = (h == 0) ? 0 : (h == Hh-1 ? 2 : 1);
        float4 spt = ((const float4*)d_spt)[h * W4 + tid];
        float sptv[4] = {spt.x, spt.y, spt.z, spt.w};
        float res[4];
        #pragma unroll
        for (int i = 0; i < 4; ++i) {
            int col = 4*tid + i;
            int cc = (col == 0) ? 0 : (col == Ww-1 ? 2 : 1);
            float s = bias + sptv[i] + sks[rc*3 + cc];
            #pragma unroll
            for (int t9 = 0; t9 < 9; ++t9) {
                int dy = t9 / 3, dx = t9 % 3;
                s += swg[t9] * sm[dy][4 + col + dx - 1];
            }
            res[i] = 1.f / (1.f + __expf(-s));
        }
        *(float4*)&satt[4*tid] = make_float4(res[0], res[1], res[2], res[3]);
    }
    __syncthreads();
    // Stream 64 channels x 176 float4 for this row.
    const float4* img4 = (const float4*)img;
    float4* out4 = (float4*)out;
    size_t base = (size_t)(cg * 64) * (HW/4) + h * W4;
    #pragma unroll 4
    for (int it = 0; it < 44; ++it) {
        int i = it * 256 + tid;                 // 0 .. 64*176-1
        int cl = i / 176, x4 = i - cl * 176;
        size_t idx = base + (size_t)cl * (HW/4) + x4;
        float4 v = __ldcs(&img4[idx]);
        float4 a = *(const float4*)&satt[4 * x4];
        __stcs(&out4[idx], make_float4(v.x*a.x, v.y*a.y, v.z*a.z, v.w*a.w));
    }
}

extern "C" void kernel_launch(void* const* d_in, const int* in_sizes, int n_in,
                              void* d_out, int out_size) {
    const float* img   = (const float*)d_in[0];
    const float* f0    = (const float*)d_in[1];
    const float* c0    = (const float*)d_in[2];
    const int*   g0    = (const int*)  d_in[3];
    const float* f1    = (const float*)d_in[4];
    const float* c1    = (const float*)d_in[5];
    const int*   g1    = (const int*)  d_in[6];
    const float* f2    = (const float*)d_in[7];
    const float* c2    = (const float*)d_in[8];
    const int*   g2    = (const int*)  d_in[9];
    const float* rd0_w = (const float*)d_in[10];
    const float* rd0_b = (const float*)d_in[11];
    const float* rd1_w = (const float*)d_in[12];
    const float* rd1_b = (const float*)d_in[13];
    const float* rd2_w = (const float*)d_in[14];
    const float* rd2_b = (const float*)d_in[15];
    const float* rd3_w = (const float*)d_in[16];
    const float* rd3_b = (const float*)d_in[17];
    const float* sp_w  = (const float*)d_in[18];
    const float* sp_b  = (const float*)d_in[19];

    int N0 = in_sizes[1] / 32;
    int N1 = in_sizes[4] / 64;
    int N2 = in_sizes[7] / 128;
    int sb0 = (N0 + 255) / 256;
    int sb1 = (N1 + 255) / 256;
    int sb2 = (N2 + 255) / 256;

    setup_kernel<<<89, 512>>>(sp_w, rd0_w, rd1_w, rd0_b, rd1_b, rd2_w, rd2_b, rd3_b);
    work_kernel<<<sb0 + sb1 + sb2 + GB, 256>>>(img, rd3_w,
                                               f0, c0, g0, N0,
                                               f1, c1, g1, N1,
                                               f2, c2, g2, N2,
                                               sb0, sb1, sb2);
    attmul_kernel<<<dim3(Hh, 4), 256>>>(img, (float*)d_out, sp_b);
}

// round 11
// speedup vs baseline: 1.3254x; 1.3254x over previous
#include <cuda_runtime.h>

#define Hh 256
#define Ww 704
#define HW (Hh*Ww)      // 180224 = 176*256*4
#define W4 (Ww/4)       // 176
#define CIMG 256
#define COUTC 131

// Scratch (device globals; no allocation allowed)
__device__ float4 d_gpart4[8 * (HW/4)];   // 8 channel-slab partial sums of gated
__device__ float d_spt[HW];
__device__ float4 d_att4[HW/4];
__device__ float d_v2[9*COUTC];
__device__ float d_u0[9*35];
__device__ float d_u1[9*67];
__device__ float d_wg[9];
__device__ float d_K[9];

// ---------------------------------------------------------------------------
// Setup: blocks 0..87 zero d_spt; blocks 88..96 fold weights for tap t=b-88.
// Per-tap work is independent: v2 row -> u0/u1 rows + wg/K.
// ---------------------------------------------------------------------------
__global__ void setup_kernel(const float* __restrict__ sp_w,
                             const float* __restrict__ rd0_w,
                             const float* __restrict__ rd1_w,
                             const float* __restrict__ rd0_b,
                             const float* __restrict__ rd1_b,
                             const float* __restrict__ rd2_w,
                             const float* __restrict__ rd2_b,
                             const float* __restrict__ rd3_b) {
    int tid = threadIdx.x;
    if (blockIdx.x < 88) {
        ((float4*)d_spt)[blockIdx.x * 512 + tid] = make_float4(0.f,0.f,0.f,0.f);
        return;
    }
    int t = blockIdx.x - 88;                  // tap 0..8
    __shared__ float spcol[COUTC];
    __shared__ float v2row[COUTC];
    if (tid < COUTC) spcol[tid] = sp_w[tid * 9 + t];
    __syncthreads();
    if (tid < COUTC) {
        float a = 0.f;
        #pragma unroll 4
        for (int c = 0; c < COUTC; ++c) a += spcol[c] * rd2_w[c * COUTC + tid];
        v2row[tid] = a;
        d_v2[t * COUTC + tid] = a;
    }
    __syncthreads();
    if (tid < 35) {
        float a = 0.f;
        #pragma unroll 4
        for (int j = 0; j < COUTC; ++j) a += v2row[j] * rd0_w[j * 35 + tid];
        d_u0[t * 35 + tid] = a;
    } else if (tid >= 64 && tid < 64 + 67) {
        int i = tid - 64;
        float a = 0.f;
        #pragma unroll 4
        for (int j = 0; j < COUTC; ++j) a += v2row[j] * rd1_w[j * 67 + i];
        d_u1[t * 67 + i] = a;
    } else if (tid == 192) {
        float w = 0.f, k = 0.f;
        #pragma unroll 4
        for (int c = 0; c < COUTC; ++c) {
            w += spcol[c];
            k += v2row[c] * (rd0_b[c] + rd1_b[c]) + spcol[c] * rd2_b[c];
        }
        d_wg[t] = w;
        d_K[t]  = k + w * rd3_b[0];
    }
}

// ---------------------------------------------------------------------------
// Gated slabs: slab cb covers channels [32cb, 32cb+32); pure streaming reduce.
// ---------------------------------------------------------------------------
__device__ __forceinline__ void gated_part(const float* __restrict__ img,
                                           const float* __restrict__ rd3_w,
                                           int b) {
    __shared__ float sw[32];
    int pb = b % 176, cb = b / 176;
    int c0 = cb * 32;
    if (threadIdx.x < 32) sw[threadIdx.x] = rd3_w[c0 + threadIdx.x];
    __syncthreads();
    int p4 = pb * 256 + threadIdx.x;
    const float4* base = (const float4*)img + (size_t)c0 * (HW/4) + p4;
    float4 acc = make_float4(0.f, 0.f, 0.f, 0.f);
    #pragma unroll
    for (int c = 0; c < 32; ++c) {
        float w = sw[c];
        float4 x = __ldcs(base + (size_t)c * (HW/4));
        acc.x += w * x.x; acc.y += w * x.y; acc.z += w * x.z; acc.w += w * x.w;
    }
    d_gpart4[cb * (HW/4) + p4] = acc;
}

// ---------------------------------------------------------------------------
// Scatter, thread-per-point: feature row loaded once per point (float4),
// tap weights via smem float4 broadcasts, 9 spread atomicAdds per point.
// ---------------------------------------------------------------------------
template<int CF>
__device__ __forceinline__ void scatter_level(const float* __restrict__ feat,
                                              const float* __restrict__ coord,
                                              const int* __restrict__ grid,
                                              int N, const float* __restrict__ u,
                                              int blockInLevel) {
    constexpr int L  = CF + 3;
    constexpr int NC = CF/4 + 1;               // float4 chunks incl. coord tail
    __shared__ __align__(16) float4 suT[NC * 9];
    for (int idx = threadIdx.x; idx < NC * 9 * 4; idx += blockDim.x) {
        int c = idx & 3, jt = idx >> 2;
        int t = jt % 9, j = jt / 9;
        int i = 4 * j + c;
        ((float*)&suT[j * 9 + t])[c] = (i < L) ? u[t * L + i] : 0.f;
    }
    __syncthreads();
    int n = blockInLevel * 256 + threadIdx.x;
    if (n >= N) return;
    float acc[9];
    #pragma unroll
    for (int t = 0; t < 9; ++t) acc[t] = 0.f;
    const float4* fp = (const float4*)(feat + (size_t)n * CF);
    #pragma unroll
    for (int j = 0; j < CF/4; ++j) {
        float4 p = __ldg(fp + j);
        #pragma unroll
        for (int t = 0; t < 9; ++t) {
            float4 w = suT[j * 9 + t];
            acc[t] += w.x*p.x + w.y*p.y + w.z*p.z + w.w*p.w;
        }
    }
    float c0 = __ldg(coord + n*3 + 0);
    float c1 = __ldg(coord + n*3 + 1);
    float c2 = __ldg(coord + n*3 + 2);
    #pragma unroll
    for (int t = 0; t < 9; ++t) {
        float4 w = suT[(CF/4) * 9 + t];
        acc[t] += w.x*c0 + w.y*c1 + w.z*c2;
    }
    int2 gxy = __ldg((const int2*)grid + n);   // (col, row)
    #pragma unroll
    for (int t = 0; t < 9; ++t) {
        int h = gxy.y - t/3 + 1;
        int w = gxy.x - t%3 + 1;
        if (h >= 0 && h < Hh && w >= 0 && w < Ww)
            atomicAdd(&d_spt[h * Ww + w], acc[t]);
    }
}

#define GB 1408   // gated blocks (176 x 8)

// Combined gated + scatter, Bresenham-interleaved roles (r8: 62.8us measured).
__global__ void work_kernel(const float* __restrict__ img, const float* __restrict__ rd3_w,
                            const float* __restrict__ f0, const float* __restrict__ c0,
                            const int* __restrict__ g0, int N0,
                            const float* __restrict__ f1, const float* __restrict__ c1,
                            const int* __restrict__ g1, int N1,
                            const float* __restrict__ f2, const float* __restrict__ c2,
                            const int* __restrict__ g2, int N2,
                            int sb0, int sb1, int sb2) {
    int SB = sb0 + sb1 + sb2;
    int total = SB + GB;
    int b = blockIdx.x;
    long long prod = (long long)b * SB;
    int sc_before = (int)(prod / total);
    int sc_incl   = (int)((prod + SB) / total);
    if (sc_incl > sc_before) {
        int s = sc_before;
        if (s < sb0) {
            scatter_level<32>(f0, c0, g0, N0, d_u0, s);
        } else if (s < sb0 + sb1) {
            scatter_level<64>(f1, c1, g1, N1, d_u1, s - sb0);
        } else {
            scatter_level<128>(f2, c2, g2, N2, d_v2, s - sb0 - sb1);
        }
    } else {
        gated_part(img, rd3_w, b - sc_before);
    }
}

// ---------------------------------------------------------------------------
// att: one row per block (176 threads). Sum 8 slabs for rows h-1..h+1 into a
// smem stencil buffer, then 9-tap with wg + boundary Ksum (computed here from
// d_K), sigmoid.
// ---------------------------------------------------------------------------
__global__ void att_kernel(const float* __restrict__ sp_b) {
    __shared__ __align__(16) float sm[3][712];   // cols at [4 .. 708)
    __shared__ float swg[9], sks[9];
    int h = blockIdx.x, t = threadIdx.x;
    if (t < 9) {
        swg[t] = d_wg[t];
        int rc = t / 3, cc = t % 3;
        float s = 0.f;
        #pragma unroll
        for (int ty = 0; ty < 3; ++ty) {
            if ((rc == 0 && ty == 0) || (rc == 2 && ty == 2)) continue;
            #pragma unroll
            for (int tx = 0; tx < 3; ++tx) {
                if ((cc == 0 && tx == 0) || (cc == 2 && tx == 2)) continue;
                s += d_K[ty*3 + tx];
            }
        }
        sks[t] = s;
    }
    #pragma unroll
    for (int r = 0; r < 3; ++r) {
        int y = h + r - 1;
        float4 s = make_float4(0.f, 0.f, 0.f, 0.f);
        if (y >= 0 && y < Hh) {
            #pragma unroll
            for (int sl = 0; sl < 8; ++sl) {
                float4 v = __ldg(&d_gpart4[sl * (HW/4) + y * W4 + t]);
                s.x += v.x; s.y += v.y; s.z += v.z; s.w += v.w;
            }
        }
        *(float4*)&sm[r][4 + 4*t] = s;
        if (t == 0) { sm[r][3] = 0.f; sm[r][708] = 0.f; }
    }
    __syncthreads();
    float bias = sp_b[0];
    int rc = (h == 0) ? 0 : (h == Hh-1 ? 2 : 1);
    float4 spt = ((const float4*)d_spt)[h * W4 + t];
    float sptv[4] = {spt.x, spt.y, spt.z, spt.w};
    float res[4];
    #pragma unroll
    for (int i = 0; i < 4; ++i) {
        int col = 4*t + i;
        int cc = (col == 0) ? 0 : (col == Ww-1 ? 2 : 1);
        float s = bias + sptv[i] + sks[rc*3 + cc];
        #pragma unroll
        for (int t9 = 0; t9 < 9; ++t9) {
            int dy = t9 / 3, dx = t9 % 3;
            s += swg[t9] * sm[dy][4 + col + dx - 1];
        }
        res[i] = 1.f / (1.f + __expf(-s));
    }
    d_att4[h * W4 + t] = make_float4(res[0], res[1], res[2], res[3]);
}

// ---------------------------------------------------------------------------
// out[c][p] = img[c][p] * att[p]; grid (176, 8), 32 channels per block.
// Fully unrolled: 32 outstanding load/store pairs per thread (MLP=32).
// ---------------------------------------------------------------------------
__global__ void mul_kernel(const float* __restrict__ img, float* __restrict__ out) {
    int p4 = blockIdx.x * 256 + threadIdx.x;
    float4 a = __ldg(&d_att4[p4]);
    size_t off = (size_t)blockIdx.y * 32 * (HW/4) + p4;
    const float4* img4 = (const float4*)img;
    float4* out4 = (float4*)out;
    #pragma unroll
    for (int c = 0; c < 32; ++c) {
        float4 v = __ldcs(&img4[off + (size_t)c * (HW/4)]);
        float4 r = make_float4(v.x * a.x, v.y * a.y, v.z * a.z, v.w * a.w);
        __stcs(&out4[off + (size_t)c * (HW/4)], r);
    }
}

extern "C" void kernel_launch(void* const* d_in, const int* in_sizes, int n_in,
                              void* d_out, int out_size) {
    const float* img   = (const float*)d_in[0];
    const float* f0    = (const float*)d_in[1];
    const float* c0    = (const float*)d_in[2];
    const int*   g0    = (const int*)  d_in[3];
    const float* f1    = (const float*)d_in[4];
    const float* c1    = (const float*)d_in[5];
    const int*   g1    = (const int*)  d_in[6];
    const float* f2    = (const float*)d_in[7];
    const float* c2    = (const float*)d_in[8];
    const int*   g2    = (const int*)  d_in[9];
    const float* rd0_w = (const float*)d_in[10];
    const float* rd0_b = (const float*)d_in[11];
    const float* rd1_w = (const float*)d_in[12];
    const float* rd1_b = (const float*)d_in[13];
    const float* rd2_w = (const float*)d_in[14];
    const float* rd2_b = (const float*)d_in[15];
    const float* rd3_w = (const float*)d_in[16];
    const float* rd3_b = (const float*)d_in[17];
    const float* sp_w  = (const float*)d_in[18];
    const float* sp_b  = (const float*)d_in[19];

    int N0 = in_sizes[1] / 32;
    int N1 = in_sizes[4] / 64;
    int N2 = in_sizes[7] / 128;
    int sb0 = (N0 + 255) / 256;
    int sb1 = (N1 + 255) / 256;
    int sb2 = (N2 + 255) / 256;

    setup_kernel<<<97, 512>>>(sp_w, rd0_w, rd1_w, rd0_b, rd1_b, rd2_w, rd2_b, rd3_b);
    work_kernel<<<sb0 + sb1 + sb2 + GB, 256>>>(img, rd3_w,
                                               f0, c0, g0, N0,
                                               f1, c1, g1, N1,
                                               f2, c2, g2, N2,
                                               sb0, sb1, sb2);
    att_kernel<<<Hh, 176>>>(sp_b);
    mul_kernel<<<dim3(176, 8), 256>>>(img, (float*)d_out);
}